// round 17
// baseline (speedup 1.0000x reference)
#include <cuda_runtime.h>
#include <cuda_fp16.h>
#include <cstdint>

// RoiAlign: feature_map (4, 256, 50, 50) f32, boxes (512,4) f32, box_idx (512) i32
// Output: (512, 256, 14, 14) f32
//
// R17: (1) one-time NCHW f32 -> NHWC fp16 transpose into static scratch;
// (2) R12-style block kernel where staging is cp.async.cg 16B per cell
// (8 contiguous channels) with commit/wait_group depth-2 pipeline.
// Fixes R13's flaw: LDG->reg->STS staging made every barrier re-expose gmem
// latency; cp.async is register-free so threads arrive at barriers instantly.

#define CROP    14
#define NPIX    (CROP * CROP)      // 196
#define FM_H    50
#define FM_W    50
#define FM_HW   (FM_H * FM_W)      // 2500
#define NCHAN   256
#define NC2     (NCHAN / 2)        // 128 half2 per pixel in NHWC
#define NBOX    512
#define CPB     32                 // channels per block
#define NCG8    (CPB / 8)          // 4 groups of 8 channels
#define WIN     16
#define NCELL   (WIN * WIN)        // 256 cells per cg region
#define THREADS 224                // 7 full warps

// Static scratch: 4 * 2500 * 128 half2 = 5.12 MB
__device__ __half2 g_nhwc[4 * FM_HW * NC2];

struct alignas(16) h2x4 { __half2 a, b, c, d; };   // 8 fp16 = one smem cell

__device__ __forceinline__ void cp_async16(uint32_t dst, const void* src) {
    asm volatile("cp.async.cg.shared.global [%0], [%1], 16;" :: "r"(dst), "l"(src));
}
__device__ __forceinline__ void cp_commit() {
    asm volatile("cp.async.commit_group;");
}
template <int N> __device__ __forceinline__ void cp_wait() {
    asm volatile("cp.async.wait_group %0;" :: "n"(N));
}

// ---------------- Kernel 1: NCHW f32 -> NHWC fp16 transpose ----------------
// Tile: 64 spatial x 64 channels. Loads coalesced along spatial; stores
// 128B-contiguous along channels.
__global__ __launch_bounds__(256) void transpose_kernel(const float* __restrict__ fm)
{
    __shared__ float tile[64][66];     // [s_local][ch_local], padded
    const int n  = blockIdx.z;
    const int s0 = blockIdx.x * 64;
    const int c0 = blockIdx.y * 64;
    const int tx = threadIdx.x;        // 64
    const int ty = threadIdx.y;        // 4
    const int tid  = ty * 64 + tx;
    const int wid  = tid >> 5;         // 0..7
    const int lane = tid & 31;

    const int s_l = s0 + tx;
    if (s_l < FM_HW) {
        #pragma unroll
        for (int i = 0; i < 16; ++i) {
            const int ch = i * 4 + ty;
            tile[tx][ch] = __ldg(fm + ((size_t)n * NCHAN + c0 + ch) * FM_HW + s_l);
        }
    }
    __syncthreads();

    #pragma unroll
    for (int sl = 0; sl < 8; ++sl) {
        const int s_local = wid * 8 + sl;
        const int s = s0 + s_local;
        if (s < FM_HW) {
            __half2 h = __floats2half2_rn(tile[s_local][2 * lane],
                                          tile[s_local][2 * lane + 1]);
            g_nhwc[((size_t)n * FM_HW + s) * NC2 + (c0 >> 1) + lane] = h;
        }
    }
}

// ---------------- Kernel 2: cp.async-staged RoiAlign ----------------
__global__ __launch_bounds__(THREADS, 9) void roi_align_kernel(
    const float* __restrict__ boxes,
    const int*   __restrict__ box_idx,
    float*       __restrict__ out)
{
    __shared__ h2x4 s4[NCG8 * NCELL];   // 16 KB

    const int m   = blockIdx.x;               // box
    const int cb  = blockIdx.y * CPB;         // channel base
    const int tid = threadIdx.x;

    // ---- Per-box geometry ----
    const float inv_stride = 1.0f / 16.0f;
    const float inv_span   = 1.0f / (float)(CROP - 1);
    const float bx1 = boxes[m * 4 + 0] * inv_stride;
    const float by1 = boxes[m * 4 + 1] * inv_stride;
    const float bx2 = boxes[m * 4 + 2] * inv_stride;
    const float by2 = boxes[m * 4 + 3] * inv_stride;

    const int ystart = min(max((int)floorf(by1), 0), FM_H - 1);
    const int xstart = min(max((int)floorf(bx1), 0), FM_W - 1);

    const int yendc = min(max((int)floorf(by2), 0), FM_H - 1);
    const int xendc = min(max((int)floorf(bx2), 0), FM_W - 1);
    const int wyn = min(yendc - ystart + 3, WIN);
    const int wxn = min(xendc - xstart + 3, WIN);
    const int cells = wyn << 4;               // task space: wyn rows x 16 slots

    const int bi = box_idx[m];
    const size_t pix_base = (size_t)bi * FM_HW;
    const int    ch2      = cb >> 1;          // half2 offset of this block's channels

    const uint32_t s4_base = (uint32_t)__cvta_generic_to_shared(s4);

    // ---- Per-pixel sampling state (valid for tid < 196) ----
    const int iy = tid / CROP;
    const int ix = tid - iy * CROP;

    const float ys = by1 + (float)iy * (by2 - by1) * inv_span;
    const float xs = bx1 + (float)ix * (bx2 - bx1) * inv_span;

    const float y0f = floorf(ys);
    const float x0f = floorf(xs);
    const int y0 = min(max((int)y0f, 0), FM_H - 1);
    const int x0 = min(max((int)x0f, 0), FM_W - 1);
    const int y1 = min(y0 + 1, FM_H - 1);
    const int x1 = min(x0 + 1, FM_W - 1);
    const float wy = ys - y0f;
    const float wx = xs - x0f;
    const float v  = (ys >= 0.0f && ys <= (float)(FM_H - 1) &&
                      xs >= 0.0f && xs <= (float)(FM_W - 1)) ? 1.0f : 0.0f;

    const int l00 = (y0 - ystart) * WIN + (x0 - xstart);
    const int dx  = x1 - x0;             // 0 or 1
    const int dyc = (y1 - y0) * WIN;     // 0 or 16

    const __half2 hw00 = __float2half2_rn((1.0f - wx) * (1.0f - wy) * v);
    const __half2 hw01 = __float2half2_rn(wx * (1.0f - wy) * v);
    const __half2 hw10 = __float2half2_rn((1.0f - wx) * wy * v);
    const __half2 hw11 = __float2half2_rn(wx * wy * v);

    float* __restrict__ o =
        out + (size_t)m * NCHAN * NPIX + (size_t)cb * NPIX + tid;

    // ---- Staging: one cp.async 16B (8 channels) per active cell ----
    auto stage_cg = [&](int cg) {
        for (int r = tid; r < cells; r += THREADS) {
            const int ry = r >> 4;
            const int rx = r & 15;
            if (rx < wxn) {
                const int gy = min(ystart + ry, FM_H - 1);
                const int gx = min(xstart + rx, FM_W - 1);
                const uint4* src =
                    (const uint4*)(g_nhwc + (pix_base + gy * FM_W + gx) * NC2 + ch2) + cg;
                cp_async16(s4_base + (uint32_t)(cg * NCELL + r) * 16u, src);
            }
        }
    };

    auto compute_cg = [&](int cg) {
        if (tid < NPIX) {
            const h2x4* sc = s4 + cg * NCELL;
            const h2x4 pa = sc[l00];
            const h2x4 pb = sc[l00 + dx];
            const h2x4 pc = sc[l00 + dyc];
            const h2x4 pd = sc[l00 + dyc + dx];

            float* oc = o + cg * 8 * NPIX;

            #pragma unroll
            for (int j = 0; j < 4; ++j) {
                __half2 u = __hfma2((&pb.a)[j], hw01, __hmul2((&pa.a)[j], hw00));
                __half2 w = __hfma2((&pd.a)[j], hw11, __hmul2((&pc.a)[j], hw10));
                __half2 r = __hadd2(u, w);
                const float2 rf = __half22float2(r);
                oc[(2 * j)     * NPIX] = rf.x;
                oc[(2 * j + 1) * NPIX] = rf.y;
            }
        }
    };

    // ---- Depth-2 async pipeline ----
    stage_cg(0); cp_commit();
    stage_cg(1); cp_commit();

    // cg = 0
    cp_wait<1>(); __syncthreads();
    stage_cg(2); cp_commit();
    compute_cg(0);
    // cg = 1
    cp_wait<1>(); __syncthreads();
    stage_cg(3); cp_commit();
    compute_cg(1);
    // cg = 2
    cp_wait<1>(); __syncthreads();
    compute_cg(2);
    // cg = 3
    cp_wait<0>(); __syncthreads();
    compute_cg(3);
}

extern "C" void kernel_launch(void* const* d_in, const int* in_sizes, int n_in,
                              void* d_out, int out_size)
{
    const float* fm     = (const float*)d_in[0];
    const float* boxes  = (const float*)d_in[1];
    const int*   boxidx = (const int*)d_in[2];
    float*       out    = (float*)d_out;

    dim3 tgrid((FM_HW + 63) / 64, NCHAN / 64, 4);   // (40, 4, 4)
    transpose_kernel<<<tgrid, dim3(64, 4)>>>(fm);

    dim3 ggrid(NBOX, NCHAN / CPB);                   // (512, 8)
    roi_align_kernel<<<ggrid, THREADS>>>(boxes, boxidx, out);
}